// round 5
// baseline (speedup 1.0000x reference)
#include <cuda_runtime.h>

#define NB    2048
#define GRID  (NB / 2)
#define KD    256
#define PD    256
#define SD    10
#define PADS  12          // xst row stride in floats (10 used + 2 pad)
#define LAMB  0.5f
#define EPSF  1e-9f
#define NEG_PAD -1e30f
#define PF    8           // prefetch depth (float2 rows of P in flight per thread)

__device__ float    g_logmse[NB];
__device__ float    g_pen[NB];
__device__ unsigned g_done = 0;

typedef unsigned long long ull;

__device__ __forceinline__ ull ffma2(ull a, ull b, ull c) {
    ull d;
    asm("fma.rn.f32x2 %0, %1, %2, %3;" : "=l"(d) : "l"(a), "l"(b), "l"(c));
    return d;
}
__device__ __forceinline__ ull pack2(float x) {
    unsigned u = __float_as_uint(x);
    ull d;
    asm("mov.b64 %0, {%1, %2};" : "=l"(d) : "r"(u), "r"(u));
    return d;
}
__device__ __forceinline__ void unpack2(ull a, float& lo, float& hi) {
    unsigned l, h;
    asm("mov.b64 {%0, %1}, %2;" : "=r"(l), "=r"(h) : "l"(a));
    lo = __uint_as_float(l);
    hi = __uint_as_float(h);
}

__global__ __launch_bounds__(256, 4)
void vil_main_kernel(const float* __restrict__ y_pred,
                     const float* __restrict__ y_true,
                     const float* __restrict__ Pmat,
                     const float* __restrict__ params,
                     const float* __restrict__ Xs,
                     float* __restrict__ out,
                     int out_size)
{
    __shared__ __align__(16) float xst[2][KD * PADS];  // X transposed+masked per half
    __shared__ __align__(16) float cp[2][SD * PD];     // masked |X@P| per half
    __shared__ float warr[2][4];
    __shared__ unsigned is_last;

    const int tid  = threadIdx.x;
    const int half = tid >> 7;          // which batch of the pair
    const int ltid = tid & 127;         // thread within half
    const int lane = tid & 31;
    const int wl   = ltid >> 5;         // warp within half: 0..3

    const int b = (blockIdx.x << 1) | half;

    int n = (int)params[b * 3 + 0];
    int k = (int)params[b * 3 + 1];
    int m = (int)params[b * 3 + 2];
    if (k > KD) k = KD;
    int pv = n - k;
    if (pv < 0) pv = 0;
    if (pv > PD) pv = PD;
    if (m < 0) m = 0;
    if (m > 8) m = 8;

    // ---- stage X transposed + masked into smem (per half) ----
    const float* Xb = Xs + (size_t)b * SD * KD;
    float* xh = xst[half];
    for (int i = ltid; i < SD * KD; i += 128) {
        int s  = i >> 8;          // KD = 256
        int kk = i & (KD - 1);
        float v = Xb[i];
        xh[kk * PADS + s] = (kk < k) ? v : 0.0f;
    }
    __syncthreads();

    // ---- GEMM: thread owns 2 adjacent columns; f32x2 packs the column pair ----
    // acc0[sp] holds (C[2s][c0], C[2s][c1])? no: acc layout = s-index x col-pair
    // accs[s] = (C[s][c0], C[s][c1]) for s = 0..9
    const int c0 = ltid << 1;
    const float* Pb = Pmat + (size_t)b * KD * PD + c0;

    ull accs[SD];
#pragma unroll
    for (int s = 0; s < SD; ++s) accs[s] = 0ull;

    ull pr[PF];
#pragma unroll
    for (int u = 0; u < PF; ++u)
        pr[u] = *reinterpret_cast<const ull*>(Pb + u * PD);   // float2 of cols (c0,c1)

    for (int kk0 = 0; kk0 < KD; kk0 += PF) {
        ull pc[PF];
#pragma unroll
        for (int u = 0; u < PF; ++u) pc[u] = pr[u];
        if (kk0 + PF < KD) {
#pragma unroll
            for (int u = 0; u < PF; ++u)
                pr[u] = *reinterpret_cast<const ull*>(Pb + (kk0 + PF + u) * PD);
        }
#pragma unroll
        for (int u = 0; u < PF; ++u) {
            const float* row = xh + (kk0 + u) * PADS;
            const float4 xa = *reinterpret_cast<const float4*>(row);      // s0..s3
            const float4 xb4 = *reinterpret_cast<const float4*>(row + 4); // s4..s7
            const float2 xc = *reinterpret_cast<const float2*>(row + 8);  // s8,s9
            const ull pp = pc[u];                                         // (P[kk][c0], P[kk][c1])
            accs[0] = ffma2(pack2(xa.x),  pp, accs[0]);
            accs[1] = ffma2(pack2(xa.y),  pp, accs[1]);
            accs[2] = ffma2(pack2(xa.z),  pp, accs[2]);
            accs[3] = ffma2(pack2(xa.w),  pp, accs[3]);
            accs[4] = ffma2(pack2(xb4.x), pp, accs[4]);
            accs[5] = ffma2(pack2(xb4.y), pp, accs[5]);
            accs[6] = ffma2(pack2(xb4.z), pp, accs[6]);
            accs[7] = ffma2(pack2(xb4.w), pp, accs[7]);
            accs[8] = ffma2(pack2(xc.x),  pp, accs[8]);
            accs[9] = ffma2(pack2(xc.y),  pp, accs[9]);
        }
    }

    // ---- write masked |C| for both columns ----
    {
        const bool ok0 = c0 < pv;
        const bool ok1 = (c0 + 1) < pv;
        float* cph = cp[half];
#pragma unroll
        for (int s = 0; s < SD; ++s) {
            float v0, v1;
            unpack2(accs[s], v0, v1);
            float2 w;
            w.x = ok0 ? fabsf(v0) : -1.0f;
            w.y = ok1 ? fabsf(v1) : -1.0f;
            *reinterpret_cast<float2*>(cph + s * PD + c0) = w;
        }
    }
    __syncthreads();

    // ---- selection: 4 warps per half, warp wl takes s = wl, wl+4, wl+8 ----
    const float* cph = cp[half];
    float s_hm = 0.0f;
    for (int s = wl; s < SD; s += 4) {
        float t[9];
#pragma unroll
        for (int i = 0; i < 9; ++i) t[i] = NEG_PAD;

        // 16 candidates per lane: 8 from X part, 8 from X@P part
#pragma unroll
        for (int j = 0; j < 8; ++j) {
            int kk = lane + 32 * j;
            float v = (kk < k) ? fabsf(xh[kk * PADS + s]) : -1.0f;
#pragma unroll
            for (int i = 8; i >= 1; --i) t[i] = fmaxf(t[i], fminf(t[i - 1], v));
            t[0] = fmaxf(t[0], v);
        }
#pragma unroll
        for (int j = 0; j < 8; ++j) {
            float v = cph[s * PD + lane + 32 * j];
#pragma unroll
            for (int i = 8; i >= 1; --i) t[i] = fmaxf(t[i], fminf(t[i - 1], v));
            t[0] = fmaxf(t[0], v);
        }

        // butterfly merge of sorted top-9 lists across 32 lanes
#pragma unroll
        for (int st = 0; st < 5; ++st) {
            float r[9], o[9];
#pragma unroll
            for (int i = 0; i < 9; ++i)
                r[i] = __shfl_xor_sync(0xffffffffu, t[i], 1 << st);
#pragma unroll
            for (int j = 0; j < 9; ++j) {
                float mx = fmaxf(t[j], r[j]);
#pragma unroll
                for (int i = 0; i < j; ++i)
                    mx = fmaxf(mx, fminf(t[i], r[j - 1 - i]));
                o[j] = mx;
            }
#pragma unroll
            for (int i = 0; i < 9; ++i) t[i] = o[i];
        }

        float topm = t[0];
#pragma unroll
        for (int i = 1; i < 9; ++i)
            if (m == i) topm = t[i];

        s_hm = fmaxf(s_hm, t[0] / (topm + EPSF));
    }
    if (lane == 0) warr[half][wl] = s_hm;
    __syncthreads();

    // ---- per-batch scalar outputs (one writer per half) ----
    if (ltid == 0) {
        float mh = fmaxf(fmaxf(warr[half][0], warr[half][1]),
                         fmaxf(warr[half][2], warr[half][3]));
        float yp = y_pred[b];
        float lt = log2f(fmaxf(y_true[b], EPSF));
        float lp = log2f(fmaxf(yp, EPSF));
        float d  = lt - lp;
        g_logmse[b] = d * d;
        bool valid  = (m + 1) <= n;
        g_pen[b]    = valid ? fmaxf(mh - yp, 0.0f) : 0.0f;
        __threadfence();
    }
    __syncthreads();

    if (tid == 0) {
        unsigned prev = atomicAdd(&g_done, 1u);
        is_last = (prev == GRID - 1) ? 1u : 0u;
    }
    __syncthreads();

    // ---- last block performs the deterministic final reduction ----
    if (is_last) {
        __threadfence();   // acquire: make all blocks' g_ writes visible
        __shared__ float sm1[256];
        __shared__ float sm2[256];
        float s1 = 0.0f, s2 = 0.0f;
        for (int i = tid; i < NB; i += 256) {   // fixed order -> deterministic
            s1 += g_logmse[i];
            s2 += g_pen[i];
        }
        sm1[tid] = s1;
        sm2[tid] = s2;
        __syncthreads();
#pragma unroll
        for (int stride = 128; stride; stride >>= 1) {
            if (tid < stride) {
                sm1[tid] += sm1[tid + stride];
                sm2[tid] += sm2[tid + stride];
            }
            __syncthreads();
        }
        if (tid == 0) {
            float logmse = sm1[0] / (float)NB;
            float viol   = sm2[0] / (float)NB;
            float total  = logmse + LAMB * viol;
            out[0] = total;
            if (out_size > 1) out[1] = logmse;
            if (out_size > 2) out[2] = viol;
            g_done = 0;   // reset for next graph replay
        }
    }
}

extern "C" void kernel_launch(void* const* d_in, const int* in_sizes, int n_in,
                              void* d_out, int out_size)
{
    const float* y_pred = (const float*)d_in[0];
    const float* y_true = (const float*)d_in[1];
    const float* Pmat   = (const float*)d_in[2];
    const float* params = (const float*)d_in[3];
    const float* Xs     = (const float*)d_in[4];

    vil_main_kernel<<<GRID, 256>>>(y_pred, y_true, Pmat, params, Xs,
                                   (float*)d_out, out_size);
}

// round 6
// speedup vs baseline: 1.0662x; 1.0662x over previous
#include <cuda_runtime.h>

#define NB    2048
#define KD    256
#define PD    256
#define SD    10
#define PADS  12          // xst row stride in floats (10 used + 2 pad)
#define LAMB  0.5f
#define EPSF  1e-9f
#define NEG_PAD -1e30f

__device__ float    g_logmse[NB];
__device__ float    g_pen[NB];
__device__ unsigned g_done = 0;

typedef unsigned long long ull;

__device__ __forceinline__ ull ffma2(ull a, ull b, ull c) {
    ull d;
    asm("fma.rn.f32x2 %0, %1, %2, %3;" : "=l"(d) : "l"(a), "l"(b), "l"(c));
    return d;
}
__device__ __forceinline__ ull pack2(float x) {
    unsigned u = __float_as_uint(x);
    ull d;
    asm("mov.b64 %0, {%1, %2};" : "=l"(d) : "r"(u), "r"(u));
    return d;
}
__device__ __forceinline__ void unpack2(ull a, float& lo, float& hi) {
    unsigned l, h;
    asm("mov.b64 {%0, %1}, %2;" : "=r"(l), "=r"(h) : "l"(a));
    lo = __uint_as_float(l);
    hi = __uint_as_float(h);
}

__global__ __launch_bounds__(256, 4)
void vil_main_kernel(const float* __restrict__ y_pred,
                     const float* __restrict__ y_true,
                     const float* __restrict__ Pmat,
                     const float* __restrict__ params,
                     const float* __restrict__ Xs,
                     float* __restrict__ out,
                     int out_size)
{
    __shared__ __align__(16) float xst[KD * PADS];   // X transposed+masked
    __shared__ __align__(16) float cp[SD * PD];      // masked |X@P|
    __shared__ float warr[8];
    __shared__ unsigned is_last;

    const int b    = blockIdx.x;
    const int tid  = threadIdx.x;
    const int lane = tid & 31;
    const int warp = tid >> 5;

    int n = (int)params[b * 3 + 0];
    int k = (int)params[b * 3 + 1];
    int m = (int)params[b * 3 + 2];
    if (k > KD) k = KD;
    int pv = n - k;
    if (pv < 0) pv = 0;
    if (pv > PD) pv = PD;
    if (m < 0) m = 0;
    if (m > 8) m = 8;

    // ---- stage X transposed + masked into smem ----
    const float* Xb = Xs + (size_t)b * SD * KD;
    for (int i = tid; i < SD * KD; i += 256) {
        int s  = i >> 8;          // KD = 256
        int kk = i & (KD - 1);
        float v = Xb[i];
        xst[kk * PADS + s] = (kk < k) ? v : 0.0f;
    }
    __syncthreads();

    // ---- GEMM: 5 packed f32x2 accumulators (s-pairs), one output column per thread
    //      P prefetched through a rolling double buffer A/B (16 rows in flight) ----
    const float* Pb = Pmat + (size_t)b * KD * PD + tid;
    ull a0 = 0ull, a1 = 0ull, a2 = 0ull, a3 = 0ull, a4 = 0ull;

    float bufA[8], bufB[8];
#pragma unroll
    for (int u = 0; u < 8; ++u) bufA[u] = Pb[u * PD];
#pragma unroll
    for (int u = 0; u < 8; ++u) bufB[u] = Pb[(8 + u) * PD];

    for (int kk0 = 0; kk0 < KD; kk0 += 16) {
        const bool moreA = (kk0 + 16) < KD;   // uniform per iteration
#pragma unroll
        for (int u = 0; u < 8; ++u) {
            const float pcur = bufA[u];
            if (moreA) bufA[u] = Pb[(kk0 + 16 + u) * PD];
            const float* row = xst + (kk0 + u) * PADS;
            ulonglong2 q0 = *reinterpret_cast<const ulonglong2*>(row);      // s0..s3
            ulonglong2 q1 = *reinterpret_cast<const ulonglong2*>(row + 4);  // s4..s7
            ull x89       = *reinterpret_cast<const ull*>(row + 8);         // s8,s9
            ull pp = pack2(pcur);
            a0 = ffma2(q0.x, pp, a0);
            a1 = ffma2(q0.y, pp, a1);
            a2 = ffma2(q1.x, pp, a2);
            a3 = ffma2(q1.y, pp, a3);
            a4 = ffma2(x89,  pp, a4);
        }
        const bool moreB = (kk0 + 24) < KD;
#pragma unroll
        for (int u = 0; u < 8; ++u) {
            const float pcur = bufB[u];
            if (moreB) bufB[u] = Pb[(kk0 + 24 + u) * PD];
            const float* row = xst + (kk0 + 8 + u) * PADS;
            ulonglong2 q0 = *reinterpret_cast<const ulonglong2*>(row);
            ulonglong2 q1 = *reinterpret_cast<const ulonglong2*>(row + 4);
            ull x89       = *reinterpret_cast<const ull*>(row + 8);
            ull pp = pack2(pcur);
            a0 = ffma2(q0.x, pp, a0);
            a1 = ffma2(q0.y, pp, a1);
            a2 = ffma2(q1.x, pp, a2);
            a3 = ffma2(q1.y, pp, a3);
            a4 = ffma2(x89,  pp, a4);
        }
    }

    // ---- write masked |C_p| to smem ----
    {
        float c[SD];
        unpack2(a0, c[0], c[1]);
        unpack2(a1, c[2], c[3]);
        unpack2(a2, c[4], c[5]);
        unpack2(a3, c[6], c[7]);
        unpack2(a4, c[8], c[9]);
        bool okp = tid < pv;
#pragma unroll
        for (int s = 0; s < SD; ++s)
            cp[s * PD + tid] = okp ? fabsf(c[s]) : -1.0f;
    }
    __syncthreads();

    // ---- selection: one warp per s (warps 0,1 take a second s) ----
    float s_hm = 0.0f;
    for (int s = warp; s < SD; s += 8) {
        float t[9];
#pragma unroll
        for (int i = 0; i < 9; ++i) t[i] = NEG_PAD;

        // 16 candidates per lane: 8 from X part, 8 from X@P part
#pragma unroll
        for (int j = 0; j < 8; ++j) {
            int kk = lane + 32 * j;
            float v = (kk < k) ? fabsf(xst[kk * PADS + s]) : -1.0f;
#pragma unroll
            for (int i = 8; i >= 1; --i) t[i] = fmaxf(t[i], fminf(t[i - 1], v));
            t[0] = fmaxf(t[0], v);
        }
#pragma unroll
        for (int j = 0; j < 8; ++j) {
            float v = cp[s * PD + lane + 32 * j];
#pragma unroll
            for (int i = 8; i >= 1; --i) t[i] = fmaxf(t[i], fminf(t[i - 1], v));
            t[0] = fmaxf(t[0], v);
        }

        // butterfly merge of sorted top-9 lists across 32 lanes
#pragma unroll
        for (int st = 0; st < 5; ++st) {
            float r[9], o[9];
#pragma unroll
            for (int i = 0; i < 9; ++i)
                r[i] = __shfl_xor_sync(0xffffffffu, t[i], 1 << st);
#pragma unroll
            for (int j = 0; j < 9; ++j) {
                float mx = fmaxf(t[j], r[j]);
#pragma unroll
                for (int i = 0; i < j; ++i)
                    mx = fmaxf(mx, fminf(t[i], r[j - 1 - i]));
                o[j] = mx;
            }
#pragma unroll
            for (int i = 0; i < 9; ++i) t[i] = o[i];
        }

        float topm = t[0];
#pragma unroll
        for (int i = 1; i < 9; ++i)
            if (m == i) topm = t[i];

        s_hm = fmaxf(s_hm, t[0] / (topm + EPSF));
    }
    if (lane == 0) warr[warp] = s_hm;
    __syncthreads();

    // ---- per-batch scalar outputs ----
    if (tid == 0) {
        float mh = warr[0];
#pragma unroll
        for (int w = 1; w < 8; ++w) mh = fmaxf(mh, warr[w]);
        float yp = y_pred[b];
        float lt = log2f(fmaxf(y_true[b], EPSF));
        float lp = log2f(fmaxf(yp, EPSF));
        float d  = lt - lp;
        g_logmse[b] = d * d;
        bool valid  = (m + 1) <= n;
        g_pen[b]    = valid ? fmaxf(mh - yp, 0.0f) : 0.0f;
        __threadfence();
        unsigned prev = atomicAdd(&g_done, 1u);
        is_last = (prev == NB - 1) ? 1u : 0u;
    }
    __syncthreads();

    // ---- last block performs the deterministic final reduction ----
    if (is_last) {
        __threadfence();   // acquire: make all blocks' g_ writes visible
        __shared__ float sm1[256];
        __shared__ float sm2[256];
        float s1 = 0.0f, s2 = 0.0f;
        for (int i = tid; i < NB; i += 256) {   // fixed order -> deterministic
            s1 += g_logmse[i];
            s2 += g_pen[i];
        }
        sm1[tid] = s1;
        sm2[tid] = s2;
        __syncthreads();
#pragma unroll
        for (int stride = 128; stride; stride >>= 1) {
            if (tid < stride) {
                sm1[tid] += sm1[tid + stride];
                sm2[tid] += sm2[tid + stride];
            }
            __syncthreads();
        }
        if (tid == 0) {
            float logmse = sm1[0] / (float)NB;
            float viol   = sm2[0] / (float)NB;
            float total  = logmse + LAMB * viol;
            out[0] = total;
            if (out_size > 1) out[1] = logmse;
            if (out_size > 2) out[2] = viol;
            g_done = 0;   // reset for next graph replay
        }
    }
}

extern "C" void kernel_launch(void* const* d_in, const int* in_sizes, int n_in,
                              void* d_out, int out_size)
{
    const float* y_pred = (const float*)d_in[0];
    const float* y_true = (const float*)d_in[1];
    const float* Pmat   = (const float*)d_in[2];
    const float* params = (const float*)d_in[3];
    const float* Xs     = (const float*)d_in[4];

    vil_main_kernel<<<NB, 256>>>(y_pred, y_true, Pmat, params, Xs,
                                 (float*)d_out, out_size);
}

// round 7
// speedup vs baseline: 1.1318x; 1.0615x over previous
#include <cuda_runtime.h>

#define NB    2048
#define GRID  (NB / 2)
#define KD    256
#define PD    256
#define SD    10
#define PADS  12          // xst row stride in floats (10 used + 2 pad)
#define LAMB  0.5f
#define EPSF  1e-9f
#define NEG_PAD -1e30f

__device__ float    g_logmse[NB];
__device__ float    g_pen[NB];
__device__ unsigned g_done = 0;

typedef unsigned long long ull;

__device__ __forceinline__ ull ffma2(ull a, ull b, ull c) {
    ull d;
    asm("fma.rn.f32x2 %0, %1, %2, %3;" : "=l"(d) : "l"(a), "l"(b), "l"(c));
    return d;
}
__device__ __forceinline__ ull pack2(float x) {
    unsigned u = __float_as_uint(x);
    ull d;
    asm("mov.b64 %0, {%1, %2};" : "=l"(d) : "r"(u), "r"(u));
    return d;
}
__device__ __forceinline__ void unpack2(ull a, float& lo, float& hi) {
    unsigned l, h;
    asm("mov.b64 {%0, %1}, %2;" : "=r"(l), "=r"(h) : "l"(a));
    lo = __uint_as_float(l);
    hi = __uint_as_float(h);
}

__global__ __launch_bounds__(256, 4)
void vil_main_kernel(const float* __restrict__ y_pred,
                     const float* __restrict__ y_true,
                     const float* __restrict__ Pmat,
                     const float* __restrict__ params,
                     const float* __restrict__ Xs,
                     float* __restrict__ out,
                     int out_size)
{
    __shared__ __align__(16) float xst[2][KD * PADS];  // X transposed+masked per half
    __shared__ __align__(16) float cp[2][SD * PD];     // masked |X@P| per half
    __shared__ float warr[2][4];
    __shared__ unsigned is_last;

    const int tid  = threadIdx.x;
    const int half = tid >> 7;          // which batch of the pair
    const int ltid = tid & 127;         // thread within half
    const int lane = tid & 31;
    const int wl   = ltid >> 5;         // warp within half: 0..3

    const int b = (blockIdx.x << 1) | half;

    int n = (int)params[b * 3 + 0];
    int k = (int)params[b * 3 + 1];
    int m = (int)params[b * 3 + 2];
    if (k > KD) k = KD;
    int pv = n - k;
    if (pv < 0) pv = 0;
    if (pv > PD) pv = PD;
    if (m < 0) m = 0;
    if (m > 8) m = 8;

    // ---- stage X transposed + masked into smem (per half) ----
    const float* Xb = Xs + (size_t)b * SD * KD;
    float* xh = xst[half];
    for (int i = ltid; i < SD * KD; i += 128) {
        int s  = i >> 8;          // KD = 256
        int kk = i & (KD - 1);
        float v = Xb[i];
        xh[kk * PADS + s] = (kk < k) ? v : 0.0f;
    }
    __syncthreads();

    // ---- GEMM: thread owns 2 adjacent columns; per column 5 f32x2 s-pair accs.
    //      P arrives as float2 (both columns) through rolling A/B double buffer ----
    const int c0 = ltid << 1;
    const float* Pb = Pmat + (size_t)b * KD * PD + c0;

    ull a0 = 0ull, a1 = 0ull, a2 = 0ull, a3 = 0ull, a4 = 0ull;  // column c0
    ull b0 = 0ull, b1 = 0ull, b2 = 0ull, b3 = 0ull, b4 = 0ull;  // column c0+1

    float2 bufA[4], bufB[4];
#pragma unroll
    for (int u = 0; u < 4; ++u)
        bufA[u] = *reinterpret_cast<const float2*>(Pb + u * PD);
#pragma unroll
    for (int u = 0; u < 4; ++u)
        bufB[u] = *reinterpret_cast<const float2*>(Pb + (4 + u) * PD);

    for (int kk0 = 0; kk0 < KD; kk0 += 8) {
        const bool moreA = (kk0 + 8) < KD;
#pragma unroll
        for (int u = 0; u < 4; ++u) {
            const float2 pcur = bufA[u];
            if (moreA)
                bufA[u] = *reinterpret_cast<const float2*>(Pb + (kk0 + 8 + u) * PD);
            const float* row = xh + (kk0 + u) * PADS;
            ulonglong2 q0 = *reinterpret_cast<const ulonglong2*>(row);      // s0..s3
            ulonglong2 q1 = *reinterpret_cast<const ulonglong2*>(row + 4);  // s4..s7
            ull x89       = *reinterpret_cast<const ull*>(row + 8);         // s8,s9
            ull pp0 = pack2(pcur.x);
            ull pp1 = pack2(pcur.y);
            a0 = ffma2(q0.x, pp0, a0);  b0 = ffma2(q0.x, pp1, b0);
            a1 = ffma2(q0.y, pp0, a1);  b1 = ffma2(q0.y, pp1, b1);
            a2 = ffma2(q1.x, pp0, a2);  b2 = ffma2(q1.x, pp1, b2);
            a3 = ffma2(q1.y, pp0, a3);  b3 = ffma2(q1.y, pp1, b3);
            a4 = ffma2(x89,  pp0, a4);  b4 = ffma2(x89,  pp1, b4);
        }
        const bool moreB = (kk0 + 12) < KD;
#pragma unroll
        for (int u = 0; u < 4; ++u) {
            const float2 pcur = bufB[u];
            if (moreB)
                bufB[u] = *reinterpret_cast<const float2*>(Pb + (kk0 + 12 + u) * PD);
            const float* row = xh + (kk0 + 4 + u) * PADS;
            ulonglong2 q0 = *reinterpret_cast<const ulonglong2*>(row);
            ulonglong2 q1 = *reinterpret_cast<const ulonglong2*>(row + 4);
            ull x89       = *reinterpret_cast<const ull*>(row + 8);
            ull pp0 = pack2(pcur.x);
            ull pp1 = pack2(pcur.y);
            a0 = ffma2(q0.x, pp0, a0);  b0 = ffma2(q0.x, pp1, b0);
            a1 = ffma2(q0.y, pp0, a1);  b1 = ffma2(q0.y, pp1, b1);
            a2 = ffma2(q1.x, pp0, a2);  b2 = ffma2(q1.x, pp1, b2);
            a3 = ffma2(q1.y, pp0, a3);  b3 = ffma2(q1.y, pp1, b3);
            a4 = ffma2(x89,  pp0, a4);  b4 = ffma2(x89,  pp1, b4);
        }
    }

    // ---- write masked |C| for both columns ----
    {
        float ca[SD], cb[SD];
        unpack2(a0, ca[0], ca[1]);  unpack2(b0, cb[0], cb[1]);
        unpack2(a1, ca[2], ca[3]);  unpack2(b1, cb[2], cb[3]);
        unpack2(a2, ca[4], ca[5]);  unpack2(b2, cb[4], cb[5]);
        unpack2(a3, ca[6], ca[7]);  unpack2(b3, cb[6], cb[7]);
        unpack2(a4, ca[8], ca[9]);  unpack2(b4, cb[8], cb[9]);
        const bool ok0 = c0 < pv;
        const bool ok1 = (c0 + 1) < pv;
        float* cph = cp[half];
#pragma unroll
        for (int s = 0; s < SD; ++s) {
            float2 w;
            w.x = ok0 ? fabsf(ca[s]) : -1.0f;
            w.y = ok1 ? fabsf(cb[s]) : -1.0f;
            *reinterpret_cast<float2*>(cph + s * PD + c0) = w;
        }
    }
    __syncthreads();

    // ---- selection: 4 warps per half, warp wl takes s = wl, wl+4, wl+8 ----
    const float* cph = cp[half];
    float s_hm = 0.0f;
    for (int s = wl; s < SD; s += 4) {
        float t[9];
#pragma unroll
        for (int i = 0; i < 9; ++i) t[i] = NEG_PAD;

        // 16 candidates per lane: 8 from X part, 8 from X@P part
#pragma unroll
        for (int j = 0; j < 8; ++j) {
            int kk = lane + 32 * j;
            float v = (kk < k) ? fabsf(xh[kk * PADS + s]) : -1.0f;
#pragma unroll
            for (int i = 8; i >= 1; --i) t[i] = fmaxf(t[i], fminf(t[i - 1], v));
            t[0] = fmaxf(t[0], v);
        }
#pragma unroll
        for (int j = 0; j < 8; ++j) {
            float v = cph[s * PD + lane + 32 * j];
#pragma unroll
            for (int i = 8; i >= 1; --i) t[i] = fmaxf(t[i], fminf(t[i - 1], v));
            t[0] = fmaxf(t[0], v);
        }

        // butterfly merge of sorted top-9 lists across 32 lanes
#pragma unroll
        for (int st = 0; st < 5; ++st) {
            float r[9], o[9];
#pragma unroll
            for (int i = 0; i < 9; ++i)
                r[i] = __shfl_xor_sync(0xffffffffu, t[i], 1 << st);
#pragma unroll
            for (int j = 0; j < 9; ++j) {
                float mx = fmaxf(t[j], r[j]);
#pragma unroll
                for (int i = 0; i < j; ++i)
                    mx = fmaxf(mx, fminf(t[i], r[j - 1 - i]));
                o[j] = mx;
            }
#pragma unroll
            for (int i = 0; i < 9; ++i) t[i] = o[i];
        }

        float topm = t[0];
#pragma unroll
        for (int i = 1; i < 9; ++i)
            if (m == i) topm = t[i];

        s_hm = fmaxf(s_hm, t[0] / (topm + EPSF));
    }
    if (lane == 0) warr[half][wl] = s_hm;
    __syncthreads();

    // ---- per-batch scalar outputs (one writer per half) ----
    if (ltid == 0) {
        float mh = fmaxf(fmaxf(warr[half][0], warr[half][1]),
                         fmaxf(warr[half][2], warr[half][3]));
        float yp = y_pred[b];
        float lt = log2f(fmaxf(y_true[b], EPSF));
        float lp = log2f(fmaxf(yp, EPSF));
        float d  = lt - lp;
        g_logmse[b] = d * d;
        bool valid  = (m + 1) <= n;
        g_pen[b]    = valid ? fmaxf(mh - yp, 0.0f) : 0.0f;
        __threadfence();
    }
    __syncthreads();

    if (tid == 0) {
        unsigned prev = atomicAdd(&g_done, 1u);
        is_last = (prev == GRID - 1) ? 1u : 0u;
    }
    __syncthreads();

    // ---- last block performs the deterministic final reduction ----
    if (is_last) {
        __threadfence();   // acquire: make all blocks' g_ writes visible
        __shared__ float sm1[256];
        __shared__ float sm2[256];
        float s1 = 0.0f, s2 = 0.0f;
        for (int i = tid; i < NB; i += 256) {   // fixed order -> deterministic
            s1 += g_logmse[i];
            s2 += g_pen[i];
        }
        sm1[tid] = s1;
        sm2[tid] = s2;
        __syncthreads();
#pragma unroll
        for (int stride = 128; stride; stride >>= 1) {
            if (tid < stride) {
                sm1[tid] += sm1[tid + stride];
                sm2[tid] += sm2[tid + stride];
            }
            __syncthreads();
        }
        if (tid == 0) {
            float logmse = sm1[0] / (float)NB;
            float viol   = sm2[0] / (float)NB;
            float total  = logmse + LAMB * viol;
            out[0] = total;
            if (out_size > 1) out[1] = logmse;
            if (out_size > 2) out[2] = viol;
            g_done = 0;   // reset for next graph replay
        }
    }
}

extern "C" void kernel_launch(void* const* d_in, const int* in_sizes, int n_in,
                              void* d_out, int out_size)
{
    const float* y_pred = (const float*)d_in[0];
    const float* y_true = (const float*)d_in[1];
    const float* Pmat   = (const float*)d_in[2];
    const float* params = (const float*)d_in[3];
    const float* Xs     = (const float*)d_in[4];

    vil_main_kernel<<<GRID, 256>>>(y_pred, y_true, Pmat, params, Xs,
                                   (float*)d_out, out_size);
}

// round 8
// speedup vs baseline: 1.1606x; 1.0254x over previous
#include <cuda_runtime.h>

#define NB    2048
#define GRID  (NB / 2)
#define KD    256
#define PD    256
#define SD    10
#define PADS  12          // xst row stride in floats (10 used + 2 pad)
#define LAMB  0.5f
#define EPSF  1e-9f
#define NEG_PAD -1e30f

__device__ float    g_logmse[NB];
__device__ float    g_pen[NB];
__device__ unsigned g_done = 0;

typedef unsigned long long ull;

__device__ __forceinline__ ull ffma2(ull a, ull b, ull c) {
    ull d;
    asm("fma.rn.f32x2 %0, %1, %2, %3;" : "=l"(d) : "l"(a), "l"(b), "l"(c));
    return d;
}
__device__ __forceinline__ ull pack2(float x) {
    unsigned u = __float_as_uint(x);
    ull d;
    asm("mov.b64 %0, {%1, %2};" : "=l"(d) : "r"(u), "r"(u));
    return d;
}
__device__ __forceinline__ void unpack2(ull a, float& lo, float& hi) {
    unsigned l, h;
    asm("mov.b64 {%0, %1}, %2;" : "=r"(l), "=r"(h) : "l"(a));
    lo = __uint_as_float(l);
    hi = __uint_as_float(h);
}

__global__ __launch_bounds__(256, 4)
void vil_main_kernel(const float* __restrict__ y_pred,
                     const float* __restrict__ y_true,
                     const float* __restrict__ Pmat,
                     const float* __restrict__ params,
                     const float* __restrict__ Xs,
                     float* __restrict__ out,
                     int out_size)
{
    __shared__ __align__(16) float xst[2][KD * PADS];  // X transposed+masked per half
    __shared__ __align__(16) float cp[2][SD * PD];     // masked |X@P| per half
    __shared__ float warr[2][4];
    __shared__ unsigned is_last;

    const int tid  = threadIdx.x;
    const int half = tid >> 7;          // which batch of the pair
    const int ltid = tid & 127;         // thread within half
    const int lane = tid & 31;
    const int wl   = ltid >> 5;         // warp within half: 0..3

    const int b = (blockIdx.x << 1) | half;

    int n = (int)params[b * 3 + 0];
    int k = (int)params[b * 3 + 1];
    int m = (int)params[b * 3 + 2];
    if (k > KD) k = KD;
    int pv = n - k;
    if (pv < 0) pv = 0;
    if (pv > PD) pv = PD;
    if (m < 0) m = 0;
    if (m > 8) m = 8;

    // ---- stage X transposed + masked into smem (per half) ----
    const float* Xb = Xs + (size_t)b * SD * KD;
    float* xh = xst[half];
    for (int i = ltid; i < SD * KD; i += 128) {
        int s  = i >> 8;          // KD = 256
        int kk = i & (KD - 1);
        float v = Xb[i];
        xh[kk * PADS + s] = (kk < k) ? v : 0.0f;
    }
    __syncthreads();

    // ---- GEMM: thread owns 2 adjacent columns; per column 5 f32x2 s-pair accs.
    //      Threads whose columns are masked out (c0 >= pv) skip the whole loop:
    //      their predicated-off LDGs fetch no sectors -> ~25% DRAM traffic cut. ----
    const int c0 = ltid << 1;
    const float* Pb = Pmat + (size_t)b * KD * PD + c0;

    ull a0 = 0ull, a1 = 0ull, a2 = 0ull, a3 = 0ull, a4 = 0ull;  // column c0
    ull b0 = 0ull, b1 = 0ull, b2 = 0ull, b3 = 0ull, b4 = 0ull;  // column c0+1

    if (c0 < pv) {
        float2 bufA[4], bufB[4];
#pragma unroll
        for (int u = 0; u < 4; ++u)
            bufA[u] = *reinterpret_cast<const float2*>(Pb + u * PD);
#pragma unroll
        for (int u = 0; u < 4; ++u)
            bufB[u] = *reinterpret_cast<const float2*>(Pb + (4 + u) * PD);

        for (int kk0 = 0; kk0 < KD; kk0 += 8) {
            const bool moreA = (kk0 + 8) < KD;
#pragma unroll
            for (int u = 0; u < 4; ++u) {
                const float2 pcur = bufA[u];
                if (moreA)
                    bufA[u] = *reinterpret_cast<const float2*>(Pb + (kk0 + 8 + u) * PD);
                const float* row = xh + (kk0 + u) * PADS;
                ulonglong2 q0 = *reinterpret_cast<const ulonglong2*>(row);      // s0..s3
                ulonglong2 q1 = *reinterpret_cast<const ulonglong2*>(row + 4);  // s4..s7
                ull x89       = *reinterpret_cast<const ull*>(row + 8);         // s8,s9
                ull pp0 = pack2(pcur.x);
                ull pp1 = pack2(pcur.y);
                a0 = ffma2(q0.x, pp0, a0);  b0 = ffma2(q0.x, pp1, b0);
                a1 = ffma2(q0.y, pp0, a1);  b1 = ffma2(q0.y, pp1, b1);
                a2 = ffma2(q1.x, pp0, a2);  b2 = ffma2(q1.x, pp1, b2);
                a3 = ffma2(q1.y, pp0, a3);  b3 = ffma2(q1.y, pp1, b3);
                a4 = ffma2(x89,  pp0, a4);  b4 = ffma2(x89,  pp1, b4);
            }
            const bool moreB = (kk0 + 12) < KD;
#pragma unroll
            for (int u = 0; u < 4; ++u) {
                const float2 pcur = bufB[u];
                if (moreB)
                    bufB[u] = *reinterpret_cast<const float2*>(Pb + (kk0 + 12 + u) * PD);
                const float* row = xh + (kk0 + 4 + u) * PADS;
                ulonglong2 q0 = *reinterpret_cast<const ulonglong2*>(row);
                ulonglong2 q1 = *reinterpret_cast<const ulonglong2*>(row + 4);
                ull x89       = *reinterpret_cast<const ull*>(row + 8);
                ull pp0 = pack2(pcur.x);
                ull pp1 = pack2(pcur.y);
                a0 = ffma2(q0.x, pp0, a0);  b0 = ffma2(q0.x, pp1, b0);
                a1 = ffma2(q0.y, pp0, a1);  b1 = ffma2(q0.y, pp1, b1);
                a2 = ffma2(q1.x, pp0, a2);  b2 = ffma2(q1.x, pp1, b2);
                a3 = ffma2(q1.y, pp0, a3);  b3 = ffma2(q1.y, pp1, b3);
                a4 = ffma2(x89,  pp0, a4);  b4 = ffma2(x89,  pp1, b4);
            }
        }
    }

    // ---- write masked |C| for both columns ----
    {
        float ca[SD], cb[SD];
        unpack2(a0, ca[0], ca[1]);  unpack2(b0, cb[0], cb[1]);
        unpack2(a1, ca[2], ca[3]);  unpack2(b1, cb[2], cb[3]);
        unpack2(a2, ca[4], ca[5]);  unpack2(b2, cb[4], cb[5]);
        unpack2(a3, ca[6], ca[7]);  unpack2(b3, cb[6], cb[7]);
        unpack2(a4, ca[8], ca[9]);  unpack2(b4, cb[8], cb[9]);
        const bool ok0 = c0 < pv;
        const bool ok1 = (c0 + 1) < pv;
        float* cph = cp[half];
#pragma unroll
        for (int s = 0; s < SD; ++s) {
            float2 w;
            w.x = ok0 ? fabsf(ca[s]) : -1.0f;
            w.y = ok1 ? fabsf(cb[s]) : -1.0f;
            *reinterpret_cast<float2*>(cph + s * PD + c0) = w;
        }
    }
    __syncthreads();

    // ---- selection: 4 warps per half, warp wl takes s = wl, wl+4, wl+8 ----
    const float* cph = cp[half];
    const int jmax = (pv + 31) >> 5;    // only scan columns < pv (rest are -1)
    float s_hm = 0.0f;
    for (int s = wl; s < SD; s += 4) {
        float t[9];
#pragma unroll
        for (int i = 0; i < 9; ++i) t[i] = NEG_PAD;

        // candidates from X part (always k=256 valid in this dataset)
#pragma unroll
        for (int j = 0; j < 8; ++j) {
            int kk = lane + 32 * j;
            float v = (kk < k) ? fabsf(xh[kk * PADS + s]) : -1.0f;
#pragma unroll
            for (int i = 8; i >= 1; --i) t[i] = fmaxf(t[i], fminf(t[i - 1], v));
            t[0] = fmaxf(t[0], v);
        }
        // candidates from X@P part, trimmed to valid columns
        for (int j = 0; j < jmax; ++j) {
            float v = cph[s * PD + lane + 32 * j];
#pragma unroll
            for (int i = 8; i >= 1; --i) t[i] = fmaxf(t[i], fminf(t[i - 1], v));
            t[0] = fmaxf(t[0], v);
        }

        // butterfly merge of sorted top-9 lists across 32 lanes
#pragma unroll
        for (int st = 0; st < 5; ++st) {
            float r[9], o[9];
#pragma unroll
            for (int i = 0; i < 9; ++i)
                r[i] = __shfl_xor_sync(0xffffffffu, t[i], 1 << st);
#pragma unroll
            for (int j = 0; j < 9; ++j) {
                float mx = fmaxf(t[j], r[j]);
#pragma unroll
                for (int i = 0; i < j; ++i)
                    mx = fmaxf(mx, fminf(t[i], r[j - 1 - i]));
                o[j] = mx;
            }
#pragma unroll
            for (int i = 0; i < 9; ++i) t[i] = o[i];
        }

        float topm = t[0];
#pragma unroll
        for (int i = 1; i < 9; ++i)
            if (m == i) topm = t[i];

        s_hm = fmaxf(s_hm, t[0] / (topm + EPSF));
    }
    if (lane == 0) warr[half][wl] = s_hm;
    __syncthreads();

    // ---- per-batch scalar outputs (one writer per half) ----
    if (ltid == 0) {
        float mh = fmaxf(fmaxf(warr[half][0], warr[half][1]),
                         fmaxf(warr[half][2], warr[half][3]));
        float yp = y_pred[b];
        float lt = log2f(fmaxf(y_true[b], EPSF));
        float lp = log2f(fmaxf(yp, EPSF));
        float d  = lt - lp;
        g_logmse[b] = d * d;
        bool valid  = (m + 1) <= n;
        g_pen[b]    = valid ? fmaxf(mh - yp, 0.0f) : 0.0f;
        __threadfence();
    }
    __syncthreads();

    if (tid == 0) {
        unsigned prev = atomicAdd(&g_done, 1u);
        is_last = (prev == GRID - 1) ? 1u : 0u;
    }
    __syncthreads();

    // ---- last block performs the deterministic final reduction ----
    if (is_last) {
        __threadfence();   // acquire: make all blocks' g_ writes visible
        __shared__ float sm1[256];
        __shared__ float sm2[256];
        float s1 = 0.0f, s2 = 0.0f;
        for (int i = tid; i < NB; i += 256) {   // fixed order -> deterministic
            s1 += g_logmse[i];
            s2 += g_pen[i];
        }
        sm1[tid] = s1;
        sm2[tid] = s2;
        __syncthreads();
#pragma unroll
        for (int stride = 128; stride; stride >>= 1) {
            if (tid < stride) {
                sm1[tid] += sm1[tid + stride];
                sm2[tid] += sm2[tid + stride];
            }
            __syncthreads();
        }
        if (tid == 0) {
            float logmse = sm1[0] / (float)NB;
            float viol   = sm2[0] / (float)NB;
            float total  = logmse + LAMB * viol;
            out[0] = total;
            if (out_size > 1) out[1] = logmse;
            if (out_size > 2) out[2] = viol;
            g_done = 0;   // reset for next graph replay
        }
    }
}

extern "C" void kernel_launch(void* const* d_in, const int* in_sizes, int n_in,
                              void* d_out, int out_size)
{
    const float* y_pred = (const float*)d_in[0];
    const float* y_true = (const float*)d_in[1];
    const float* Pmat   = (const float*)d_in[2];
    const float* params = (const float*)d_in[3];
    const float* Xs     = (const float*)d_in[4];

    vil_main_kernel<<<GRID, 256>>>(y_pred, y_true, Pmat, params, Xs,
                                   (float*)d_out, out_size);
}